// round 1
// baseline (speedup 1.0000x reference)
#include <cuda_runtime.h>

#define TS_X 32
#define TS_Y 8
#define PAD 3
#define SW (TS_X + 2*PAD)   // 38
#define SH (TS_Y + 2*PAD)   // 14
#define IMG_W 512
#define IMG_H 512

__constant__ float c_mean[3] = {0.485f, 0.456f, 0.406f};
__constant__ float c_std[3]  = {0.229f, 0.224f, 0.225f};

__device__ __forceinline__ void s2(float& a, float& b) {
    float t = fminf(a, b);
    b = fmaxf(a, b);
    a = t;
}

__global__ __launch_bounds__(TS_X * TS_Y) void median7_kernel(
    const float* __restrict__ in, float* __restrict__ out)
{
    __shared__ float tile[SH][SW];

    const int z = blockIdx.z;                 // plane index: b*3 + c
    const int c = z % 3;
    const float* img = in + (size_t)z * (IMG_W * IMG_H);
    float* o = out + (size_t)z * (IMG_W * IMG_H);

    const int tx0 = blockIdx.x * TS_X;
    const int ty0 = blockIdx.y * TS_Y;
    const int tid = threadIdx.y * TS_X + threadIdx.x;

    // Cooperative load of (TS_X+6)x(TS_Y+6) tile with reflect padding
    #pragma unroll
    for (int i = tid; i < SW * SH; i += TS_X * TS_Y) {
        int ly = i / SW, lx = i % SW;
        int gy = ty0 + ly - PAD;
        int gx = tx0 + lx - PAD;
        gy = gy < 0 ? -gy : (gy >= IMG_H ? 2 * (IMG_H - 1) - gy : gy);
        gx = gx < 0 ? -gx : (gx >= IMG_W ? 2 * (IMG_W - 1) - gx : gx);
        tile[ly][lx] = img[gy * IMG_W + gx];
    }
    __syncthreads();

    const int lx = threadIdx.x;
    const int ly = threadIdx.y;

    // Forgetful selection: buffer of 26 = ceil(49/2)+1
    float b[26];
    #pragma unroll
    for (int p = 0; p < 26; ++p)
        b[p] = tile[ly + p / 7][lx + p % 7];

    #pragma unroll
    for (int p = 26; p < 49; ++p) {
        const int m = 52 - p;   // current buffer size (26 down to 4)
        // pairwise compare-exchange
        #pragma unroll
        for (int j = 0; j + 1 < m; j += 2) s2(b[j], b[j + 1]);
        // min chain over even slots (includes odd-m leftover) -> global min at b[0]
        #pragma unroll
        for (int j = 2; j < m; j += 2) s2(b[0], b[j]);
        // max chain over odd slots into b[m-1] -> global max at b[m-1]
        #pragma unroll
        for (int j = 1; j < m - 1; j += 2) s2(b[j], b[m - 1]);
        // discard min (overwrite b[0]) and max (shrink: b[m-1] dropped)
        b[0] = tile[ly + p / 7][lx + p % 7];
    }
    // 3 elements remain in b[0..2]
    s2(b[0], b[1]); s2(b[1], b[2]); s2(b[0], b[1]);
    const float med = b[1];

    // Apply monotone transform g(v) = (clip(v*std+mean,0,1)-mean)/std
    const float mu = c_mean[c], sd = c_std[c];
    float u = fmaf(med, sd, mu);
    u = fminf(fmaxf(u, 0.0f), 1.0f);
    const float res = (u - mu) / sd;

    const int gx = tx0 + lx;
    const int gy = ty0 + ly;
    o[gy * IMG_W + gx] = res;
}

extern "C" void kernel_launch(void* const* d_in, const int* in_sizes, int n_in,
                              void* d_out, int out_size)
{
    const float* image = (const float*)d_in[0];
    const float* mask  = (const float*)d_in[1];
    float* out = (float*)d_out;

    const int img_elems  = in_sizes[0];              // 8*3*512*512
    const int mask_elems = in_sizes[1];              // 8*1*512*512
    const int planes = img_elems / (IMG_W * IMG_H);  // 24

    dim3 block(TS_X, TS_Y);
    dim3 grid(IMG_W / TS_X, IMG_H / TS_Y, planes);
    median7_kernel<<<grid, block>>>(image, out);

    // mask passthrough (tuple element 2), device-to-device async copy
    cudaMemcpyAsync(out + img_elems, mask,
                    (size_t)mask_elems * sizeof(float),
                    cudaMemcpyDeviceToDevice, 0);
}

// round 2
// speedup vs baseline: 1.7656x; 1.7656x over previous
#include <cuda_runtime.h>

#define TS_X 32
#define TS_Y 8            // threads in y; each thread does 2 output rows
#define ROWS_PER_T 2
#define TILE_H (TS_Y * ROWS_PER_T)   // 16 output rows per block
#define PAD 3
#define SW (TS_X + 2*PAD)   // 38
#define SH (TILE_H + 2*PAD) // 22
#define IMG_W 512
#define IMG_H 512

__constant__ float c_mean[3] = {0.485f, 0.456f, 0.406f};
__constant__ float c_std[3]  = {0.229f, 0.224f, 0.225f};

__device__ __forceinline__ void s2(float& a, float& b) {
    float t = fminf(a, b);
    b = fmaxf(a, b);
    a = t;
}

// On buffer of (compile-time-constant after unroll) size m:
// leaves global min at b[0], global max at b[m-1].
#define MINMAX_REDUCE(b, m)                                        \
    do {                                                           \
        _Pragma("unroll")                                          \
        for (int j = 0; j + 1 < (m); j += 2) s2(b[j], b[j + 1]);   \
        _Pragma("unroll")                                          \
        for (int j = 2; j < (m); j += 2) s2(b[0], b[j]);           \
        _Pragma("unroll")                                          \
        for (int j = 1; j < (m) - 1; j += 2) s2(b[j], b[(m) - 1]); \
    } while (0)

__global__ __launch_bounds__(TS_X * TS_Y) void median7_kernel(
    const float* __restrict__ in, float* __restrict__ out)
{
    __shared__ float tile[SH][SW];

    const int z = blockIdx.z;                 // plane index: b*3 + c
    const int c = z % 3;
    const float* img = in + (size_t)z * (IMG_W * IMG_H);
    float* o = out + (size_t)z * (IMG_W * IMG_H);

    const int tx0 = blockIdx.x * TS_X;
    const int ty0 = blockIdx.y * TILE_H;
    const int tid = threadIdx.y * TS_X + threadIdx.x;

    // Cooperative load of (TS_X+6)x(TILE_H+6) tile with reflect padding
    #pragma unroll
    for (int i = tid; i < SW * SH; i += TS_X * TS_Y) {
        int ly = i / SW, lx = i % SW;
        int gy = ty0 + ly - PAD;
        int gx = tx0 + lx - PAD;
        gy = gy < 0 ? -gy : (gy >= IMG_H ? 2 * (IMG_H - 1) - gy : gy);
        gx = gx < 0 ? -gx : (gx >= IMG_W ? 2 * (IMG_W - 1) - gx : gx);
        tile[ly][lx] = img[gy * IMG_W + gx];
    }
    __syncthreads();

    const int lx = threadIdx.x;
    const int ly = ROWS_PER_T * threadIdx.y;  // tile-row of first output's window top

    // ---- Shared phase: forgetful selection over the 42 common elements ----
    // Common rows (shared by both output pixels): tile rows ly+1 .. ly+6.
    // Buffer 26 -> 10, discarding 16 below-median and 16 above-median elems.
    float b[26];
    #pragma unroll
    for (int p = 0; p < 26; ++p)
        b[p] = tile[ly + 1 + p / 7][lx + p % 7];

    #pragma unroll
    for (int p = 26; p < 42; ++p) {
        const int m = 52 - p;   // 26 down to 11
        MINMAX_REDUCE(b, m);
        b[0] = tile[ly + 1 + p / 7][lx + p % 7];  // discard min (overwrite) & max (shrink)
    }
    // b[0..9]: 10 surviving candidates; median of 49 == median of (these 10 + 7 private)

    const float mu = c_mean[c], sd = c_std[c];
    const int gx = tx0 + lx;
    const int gy0 = ty0 + ly;

    #pragma unroll
    for (int px = 0; px < ROWS_PER_T; ++px) {
        // Private row: tile row ly+0 for pixel0 (window top), ly+7 for pixel1 (window bottom)
        const int prow = (px == 0) ? ly : (ly + 7);

        float t[10];
        #pragma unroll
        for (int j = 0; j < 10; ++j) t[j] = b[j];

        #pragma unroll
        for (int s = 0; s < 7; ++s) {
            const int m = 10 - s;   // 10 down to 4
            MINMAX_REDUCE(t, m);
            t[0] = tile[prow][lx + s];
        }
        // 3 remain
        s2(t[0], t[1]); s2(t[1], t[2]); s2(t[0], t[1]);
        const float med = t[1];

        // Monotone transform g(v) = (clip(v*std+mean,0,1)-mean)/std
        float u = fmaf(med, sd, mu);
        u = fminf(fmaxf(u, 0.0f), 1.0f);
        o[(gy0 + px) * IMG_W + gx] = (u - mu) / sd;
    }
}

extern "C" void kernel_launch(void* const* d_in, const int* in_sizes, int n_in,
                              void* d_out, int out_size)
{
    const float* image = (const float*)d_in[0];
    const float* mask  = (const float*)d_in[1];
    float* out = (float*)d_out;

    const int img_elems  = in_sizes[0];              // 8*3*512*512
    const int mask_elems = in_sizes[1];              // 8*1*512*512
    const int planes = img_elems / (IMG_W * IMG_H);  // 24

    dim3 block(TS_X, TS_Y);
    dim3 grid(IMG_W / TS_X, IMG_H / TILE_H, planes);
    median7_kernel<<<grid, block>>>(image, out);

    // mask passthrough, device-to-device async copy
    cudaMemcpyAsync(out + img_elems, mask,
                    (size_t)mask_elems * sizeof(float),
                    cudaMemcpyDeviceToDevice, 0);
}

// round 4
// speedup vs baseline: 2.1496x; 1.2175x over previous
#include <cuda_runtime.h>

#define TS_X 32
#define TS_Y 8            // threads in y; each thread does 2 output rows
#define ROWS_PER_T 2
#define TILE_H (TS_Y * ROWS_PER_T)   // 16 output rows per block
#define PAD 3
#define SW (TS_X + 2*PAD)   // 38
#define SH (TILE_H + 2*PAD) // 22
#define IMG_W 512
#define IMG_H 512

__constant__ float c_mean[3] = {0.485f, 0.456f, 0.406f};
__constant__ float c_std[3]  = {0.229f, 0.224f, 0.225f};

// Pure compare-exchange: 2 FMNMX (alu pipe)
__device__ __forceinline__ void s2(float& a, float& b) {
    float t = fminf(a, b);
    b = fmaxf(a, b);
    a = t;
}

// Hybrid compare-exchange: 1 FMNMX (alu) + 2 FADD (fma pipe).
// max = (a+b) - min(a,b); exact to ~1 ulp for finite inputs.
__device__ __forceinline__ void s2h(float& a, float& b) {
    float s  = a + b;        // FADD  (fma pipe)
    float mn = fminf(a, b);  // FMNMX (alu pipe)
    b = s - mn;              // FADD  (fma pipe)
    a = mn;
}

// Compile-time selection: 2/3 hybrid, 1/3 pure, spread across the network.
#define CE(a, b, idx)                              \
    do {                                           \
        if (((idx) % 3) == 0) s2(a, b);            \
        else                  s2h(a, b);           \
    } while (0)

// Leaves global min at b[0], global max at b[m-1].
#define MINMAX_REDUCE(b, m)                                               \
    do {                                                                  \
        _Pragma("unroll")                                                 \
        for (int j = 0; j + 1 < (m); j += 2) CE(b[j], b[j + 1], j >> 1);  \
        _Pragma("unroll")                                                 \
        for (int j = 2; j < (m); j += 2) CE(b[0], b[j], j >> 1);          \
        _Pragma("unroll")                                                 \
        for (int j = 1; j < (m) - 1; j += 2) CE(b[j], b[(m) - 1], j >> 1);\
    } while (0)

__global__ __launch_bounds__(TS_X * TS_Y) void median7_kernel(
    const float* __restrict__ in, float* __restrict__ out)
{
    __shared__ float tile[SH][SW];

    const int z = blockIdx.z;                 // plane index: b*3 + c
    const int c = z % 3;
    const float* img = in + (size_t)z * (IMG_W * IMG_H);
    float* o = out + (size_t)z * (IMG_W * IMG_H);

    const int tx0 = blockIdx.x * TS_X;
    const int ty0 = blockIdx.y * TILE_H;
    const int tid = threadIdx.y * TS_X + threadIdx.x;

    // Cooperative load of (TS_X+6)x(TILE_H+6) tile with reflect padding
    #pragma unroll
    for (int i = tid; i < SW * SH; i += TS_X * TS_Y) {
        int ly = i / SW, lx = i % SW;
        int gy = ty0 + ly - PAD;
        int gx = tx0 + lx - PAD;
        gy = gy < 0 ? -gy : (gy >= IMG_H ? 2 * (IMG_H - 1) - gy : gy);
        gx = gx < 0 ? -gx : (gx >= IMG_W ? 2 * (IMG_W - 1) - gx : gx);
        tile[ly][lx] = img[gy * IMG_W + gx];
    }
    __syncthreads();

    const int lx = threadIdx.x;
    const int ly = ROWS_PER_T * threadIdx.y;  // tile-row of first output's window top

    // ---- Shared phase: forgetful selection over the 42 common elements ----
    // Common rows (shared by both output pixels): tile rows ly+1 .. ly+6.
    float b[26];
    #pragma unroll
    for (int p = 0; p < 26; ++p)
        b[p] = tile[ly + 1 + p / 7][lx + p % 7];

    #pragma unroll
    for (int p = 26; p < 42; ++p) {
        const int m = 52 - p;   // 26 down to 11
        MINMAX_REDUCE(b, m);
        b[0] = tile[ly + 1 + p / 7][lx + p % 7];  // discard min (overwrite) & max (shrink)
    }
    // b[0..9]: 10 survivors; median of 49 == median of (these 10 + 7 private)

    const float mu = c_mean[c], sd = c_std[c];
    const float inv_sd = 1.0f / sd;
    const int gx = tx0 + lx;
    const int gy0 = ty0 + ly;

    #pragma unroll
    for (int px = 0; px < ROWS_PER_T; ++px) {
        const int prow = (px == 0) ? ly : (ly + 7);

        float t[10];
        #pragma unroll
        for (int j = 0; j < 10; ++j) t[j] = b[j];

        #pragma unroll
        for (int s = 0; s < 7; ++s) {
            const int m = 10 - s;   // 10 down to 4
            MINMAX_REDUCE(t, m);
            t[0] = tile[prow][lx + s];
        }
        // 3 remain
        s2(t[0], t[1]); s2h(t[1], t[2]); s2(t[0], t[1]);
        const float med = t[1];

        // Monotone transform g(v) = (clip(v*std+mean,0,1)-mean)/std
        float u = fmaf(med, sd, mu);
        u = fminf(fmaxf(u, 0.0f), 1.0f);
        o[(gy0 + px) * IMG_W + gx] = (u - mu) * inv_sd;
    }
}

extern "C" void kernel_launch(void* const* d_in, const int* in_sizes, int n_in,
                              void* d_out, int out_size)
{
    const float* image = (const float*)d_in[0];
    const float* mask  = (const float*)d_in[1];
    float* out = (float*)d_out;

    const int img_elems  = in_sizes[0];              // 8*3*512*512
    const int mask_elems = in_sizes[1];              // 8*1*512*512
    const int planes = img_elems / (IMG_W * IMG_H);  // 24

    dim3 block(TS_X, TS_Y);
    dim3 grid(IMG_W / TS_X, IMG_H / TILE_H, planes);
    median7_kernel<<<grid, block>>>(image, out);

    // mask passthrough, device-to-device async copy
    cudaMemcpyAsync(out + img_elems, mask,
                    (size_t)mask_elems * sizeof(float),
                    cudaMemcpyDeviceToDevice, 0);
}

// round 6
// speedup vs baseline: 3.2557x; 1.5145x over previous
#include <cuda_runtime.h>
#include <cuda_fp16.h>
#include <stdint.h>

#define TS_X 32
#define TS_Y 8
#define ROWS_PER_T 2
#define HALF_H 16                 // output rows per half-tile
#define TILE_H 32                 // total output rows per block (2 halves in f16x2 lanes)
#define PAD 3
#define SW (TS_X + 2*PAD)         // 38
#define SH (HALF_H + 2*PAD)       // 22
#define IMG_W 512
#define IMG_H 512

__constant__ float c_mean[3] = {0.485f, 0.456f, 0.406f};
__constant__ float c_std[3]  = {0.229f, 0.224f, 0.225f};

// Pure packed compare-exchange: selection only, per-lane exact on fp16 values.
__device__ __forceinline__ void s2(__half2& a, __half2& b) {
    __half2 mn = __hmin2(a, b);
    b = __hmax2(a, b);
    a = mn;
}

// Leaves per-lane min at b[0], per-lane max at b[m-1].
#define MINMAX_REDUCE(b, m)                                        \
    do {                                                           \
        _Pragma("unroll")                                          \
        for (int j = 0; j + 1 < (m); j += 2) s2(b[j], b[j + 1]);   \
        _Pragma("unroll")                                          \
        for (int j = 2; j < (m); j += 2) s2(b[0], b[j]);           \
        _Pragma("unroll")                                          \
        for (int j = 1; j < (m) - 1; j += 2) s2(b[j], b[(m) - 1]); \
    } while (0)

__device__ __forceinline__ int reflect(int v, int n) {
    v = v < 0 ? -v : v;
    return v >= n ? 2 * (n - 1) - v : v;
}

__global__ __launch_bounds__(TS_X * TS_Y) void median7_kernel(
    const float* __restrict__ in, float* __restrict__ out)
{
    __shared__ __half2 tile[SH][SW];

    const int z = blockIdx.z;                 // plane: b*3 + c
    const int c = z % 3;
    const float* img = in + (size_t)z * (IMG_W * IMG_H);
    float* o = out + (size_t)z * (IMG_W * IMG_H);

    const int tx0 = blockIdx.x * TS_X;
    const int ty0 = blockIdx.y * TILE_H;
    const int tid = threadIdx.y * TS_X + threadIdx.x;

    // Load (TS_X+6)x(HALF_H+6) tile; lane.lo = upper half rows, lane.hi = lower half rows
    #pragma unroll
    for (int i = tid; i < SW * SH; i += TS_X * TS_Y) {
        const int r = i / SW, lxx = i % SW;
        const int gx  = reflect(tx0 + lxx - PAD, IMG_W);
        const int gyA = reflect(ty0 + r - PAD, IMG_H);
        const int gyB = reflect(ty0 + HALF_H + r - PAD, IMG_H);
        const float vA = img[gyA * IMG_W + gx];
        const float vB = img[gyB * IMG_W + gx];
        tile[r][lxx] = __floats2half2_rn(vA, vB);
    }
    __syncthreads();

    const int lx = threadIdx.x;
    const int wy = ROWS_PER_T * threadIdx.y;  // output row (within half-tile) of pair's first pixel

    // ---- Shared phase over the 42 common elements (rows wy+1..wy+6 of tile) ----
    __half2 b[26];
    #pragma unroll
    for (int p = 0; p < 26; ++p)
        b[p] = tile[wy + 1 + p / 7][lx + p % 7];

    #pragma unroll
    for (int p = 26; p < 42; ++p) {
        const int m = 52 - p;   // 26 down to 11
        MINMAX_REDUCE(b, m);
        b[0] = tile[wy + 1 + p / 7][lx + p % 7];
    }
    // b[0..9]: 10 survivors (per fp16 lane)

    const float mu = c_mean[c], sd = c_std[c];
    const float inv_sd = 1.0f / sd;
    const int gx = tx0 + lx;

    #pragma unroll
    for (int px = 0; px < ROWS_PER_T; ++px) {
        const int prow = (px == 0) ? wy : (wy + 7);

        __half2 t[10];
        #pragma unroll
        for (int j = 0; j < 10; ++j) t[j] = b[j];

        #pragma unroll
        for (int s = 0; s < 7; ++s) {
            const int m = 10 - s;   // 10 down to 4
            MINMAX_REDUCE(t, m);
            t[0] = tile[prow][lx + s];
        }
        s2(t[0], t[1]); s2(t[1], t[2]); s2(t[0], t[1]);
        const __half2 med2 = t[1];

        // Two output pixels: same x, rows (ty0+wy+px) and (ty0+HALF_H+wy+px)
        const float medA = __low2float(med2);
        const float medB = __high2float(med2);

        float uA = fmaf(medA, sd, mu);
        uA = fminf(fmaxf(uA, 0.0f), 1.0f);
        o[(ty0 + wy + px) * IMG_W + gx] = (uA - mu) * inv_sd;

        float uB = fmaf(medB, sd, mu);
        uB = fminf(fmaxf(uB, 0.0f), 1.0f);
        o[(ty0 + HALF_H + wy + px) * IMG_W + gx] = (uB - mu) * inv_sd;
    }
}

extern "C" void kernel_launch(void* const* d_in, const int* in_sizes, int n_in,
                              void* d_out, int out_size)
{
    const float* image = (const float*)d_in[0];
    const float* mask  = (const float*)d_in[1];
    float* out = (float*)d_out;

    const int img_elems  = in_sizes[0];              // 8*3*512*512
    const int mask_elems = in_sizes[1];              // 8*1*512*512
    const int planes = img_elems / (IMG_W * IMG_H);  // 24

    dim3 block(TS_X, TS_Y);
    dim3 grid(IMG_W / TS_X, IMG_H / TILE_H, planes);
    median7_kernel<<<grid, block>>>(image, out);

    cudaMemcpyAsync(out + img_elems, mask,
                    (size_t)mask_elems * sizeof(float),
                    cudaMemcpyDeviceToDevice, 0);
}

// round 10
// speedup vs baseline: 5.8769x; 1.8051x over previous
#include <cuda_runtime.h>
#include <cuda_fp16.h>
#include <stdint.h>

#define TS_X 32
#define TS_Y 8
#define ROWS_PER_T 4               // output rows per thread (per fp16 lane)
#define HALF_H (TS_Y * ROWS_PER_T) // 32
#define TILE_H (2 * HALF_H)        // 64 output rows per block (2 fp16 lanes)
#define PAD 3
#define SW (TS_X + 2*PAD)          // 38
#define SH (HALF_H + 2*PAD)        // 38
#define IMG_W 512
#define IMG_H 512

__constant__ float c_mean[3] = {0.485f, 0.456f, 0.406f};
__constant__ float c_std[3]  = {0.229f, 0.224f, 0.225f};

// ---------------- compile-time network generation ----------------
struct Op { unsigned char k, a, b; };   // k=0: CE(buf[a],buf[b]); k=1: buf[b]=buf[a]
struct IL { unsigned char v[44]; int n; };
struct Prog { Op ops[900]; int n; unsigned char med[4]; };

__host__ __device__ static constexpr IL make_row(int r) {
    IL x{}; for (int c = 0; c < 7; ++c) x.v[x.n++] = (unsigned char)(r * 7 + c);
    return x;
}

// Batcher odd-even merge of two sorted index lists; emits comparators,
// returns the slot indices in sorted order.
__host__ __device__ static constexpr IL oem(const IL A, const IL B, Prog& P) {
    if (A.n == 0) return B;
    if (B.n == 0) return A;
    IL R{};
    if (A.n == 1 && B.n == 1) {
        P.ops[P.n++] = {0, A.v[0], B.v[0]};
        R.v[0] = A.v[0]; R.v[1] = B.v[0]; R.n = 2; return R;
    }
    IL Ae{}, Ao{}, Be{}, Bo{};
    for (int i = 0; i < A.n; ++i) { if (i % 2 == 0) Ae.v[Ae.n++] = A.v[i]; else Ao.v[Ao.n++] = A.v[i]; }
    for (int i = 0; i < B.n; ++i) { if (i % 2 == 0) Be.v[Be.n++] = B.v[i]; else Bo.v[Bo.n++] = B.v[i]; }
    IL E = oem(Ae, Be, P);
    IL O = oem(Ao, Bo, P);
    R.v[R.n++] = E.v[0];
    int i = 1, j = 0;
    while (i < E.n && j < O.n) {
        P.ops[P.n++] = {0, O.v[j], E.v[i]};     // min -> O slot, max -> E slot
        R.v[R.n++] = O.v[j]; R.v[R.n++] = E.v[i];
        ++i; ++j;
    }
    while (j < O.n) R.v[R.n++] = O.v[j++];
    while (i < E.n) R.v[R.n++] = E.v[i++];
    return R;
}

__host__ __device__ static constexpr IL sort_gen(const IL A, Prog& P) {
    if (A.n <= 1) return A;
    IL L{}, R{};
    const int m = A.n / 2;
    for (int i = 0; i < m;   ++i) L.v[L.n++] = A.v[i];
    for (int i = m; i < A.n; ++i) R.v[R.n++] = A.v[i];
    IL Ls = sort_gen(L, P), Rs = sort_gen(R, P);
    return oem(Ls, Rs, P);
}

__host__ __device__ static constexpr IL copy_gen(const IL A, int dst0, Prog& P) {
    IL R{};
    for (int i = 0; i < A.n; ++i) {
        P.ops[P.n++] = {1, A.v[i], (unsigned char)(dst0 + i)};
        R.v[R.n++] = (unsigned char)(dst0 + i);
    }
    return R;
}

__host__ __device__ static constexpr IL sub(const IL A, int lo, int cnt) {
    IL R{}; for (int i = 0; i < cnt; ++i) R.v[R.n++] = A.v[lo + i]; return R;
}

// Thread does 4 output rows: pairs (0,1) and (2,3). Tile rows 0..9 (relative).
// Pair1 shared rows 1..6, privates rows 0,7. Pair2 shared rows 3..8, privates 2,9.
// Blocks: Ba=(1,2) Bb=(3,4) Bc=(5,6) Bd=(7,8); M=merge(Bb,Bc) shared by both pairs.
__host__ __device__ static constexpr Prog build() {
    Prog P{};
    IL L[10]{};
    for (int r = 0; r < 10; ++r) L[r] = sort_gen(make_row(r), P);
    IL c2 = copy_gen(L[2], 70, P);      // preserve sorted rows consumed by blocks
    IL c7 = copy_gen(L[7], 77, P);
    IL Ba = oem(L[1], L[2], P);
    IL Bb = oem(L[3], L[4], P);
    IL Bc = oem(L[5], L[6], P);
    IL Bd = oem(L[7], L[8], P);
    IL M  = oem(Bb, Bc, P);             // 28, shared
    IL Mc = copy_gen(M, 84, P);
    IL F1 = oem(Mc, Ba, P);             // sorted 42 for pair1
    IL F2 = oem(M,  Bd, P);             // sorted 42 for pair2
    IL m1 = sub(F1, 16, 10);            // ranks 17..26 of 42: only possible medians
    IL m2 = sub(F2, 16, 10);
    IL m1c = copy_gen(m1, 112, P);
    IL m2c = copy_gen(m2, 122, P);
    IL G0 = oem(m1,  L[0], P); P.med[0] = G0.v[8];   // rank 25 of 49 = rank 9 of 17
    IL G1 = oem(m1c, c7,   P); P.med[1] = G1.v[8];
    IL G2 = oem(m2,  c2,   P); P.med[2] = G2.v[8];
    IL G3 = oem(m2c, L[9], P); P.med[3] = G3.v[8];
    return P;
}

// ---------------- kernel ----------------
__device__ __forceinline__ void s2(__half2& a, __half2& b) {
    __half2 mn = __hmin2(a, b);
    b = __hmax2(a, b);
    a = mn;
}

__device__ __forceinline__ int reflect(int v, int n) {
    v = v < 0 ? -v : v;
    return v >= n ? 2 * (n - 1) - v : v;
}

__global__ __launch_bounds__(TS_X * TS_Y) void median7_kernel(
    const float* __restrict__ in, float* __restrict__ out)
{
    // Local constexpr: evaluated at compile time; all accesses below use
    // literal indices after full unroll, so it folds to straight-line code.
    constexpr Prog PROG = build();

    __shared__ __half2 tile[SH][SW];

    const int z = blockIdx.z;
    const int c = z % 3;
    const float* img = in + (size_t)z * (IMG_W * IMG_H);
    float* o = out + (size_t)z * (IMG_W * IMG_H);

    const int tx0 = blockIdx.x * TS_X;
    const int ty0 = blockIdx.y * TILE_H;
    const int tid = threadIdx.y * TS_X + threadIdx.x;

    #pragma unroll
    for (int i = tid; i < SW * SH; i += TS_X * TS_Y) {
        const int r = i / SW, lxx = i % SW;
        const int gx  = reflect(tx0 + lxx - PAD, IMG_W);
        const int gyA = reflect(ty0 + r - PAD, IMG_H);
        const int gyB = reflect(ty0 + HALF_H + r - PAD, IMG_H);
        tile[r][lxx] = __floats2half2_rn(img[gyA * IMG_W + gx], img[gyB * IMG_W + gx]);
    }
    __syncthreads();

    const int lx = threadIdx.x;
    const int wy = ROWS_PER_T * threadIdx.y;   // first output row (tile row offset)

    __half2 buf[132];
    #pragma unroll
    for (int r = 0; r < 10; ++r)
        #pragma unroll
        for (int cc = 0; cc < 7; ++cc)
            buf[r * 7 + cc] = tile[wy + r][lx + cc];

    #pragma unroll
    for (int k = 0; k < PROG.n; ++k) {
        if (PROG.ops[k].k == 0) s2(buf[PROG.ops[k].a], buf[PROG.ops[k].b]);
        else                    buf[PROG.ops[k].b] = buf[PROG.ops[k].a];
    }

    const float mu = c_mean[c], sd = c_std[c];
    const float inv_sd = 1.0f / sd;
    const int gx = tx0 + lx;

    #pragma unroll
    for (int px = 0; px < ROWS_PER_T; ++px) {
        const __half2 med2 = buf[PROG.med[px]];
        const float medA = __low2float(med2);
        const float medB = __high2float(med2);

        float uA = fmaf(medA, sd, mu);
        uA = fminf(fmaxf(uA, 0.0f), 1.0f);
        o[(ty0 + wy + px) * IMG_W + gx] = (uA - mu) * inv_sd;

        float uB = fmaf(medB, sd, mu);
        uB = fminf(fmaxf(uB, 0.0f), 1.0f);
        o[(ty0 + HALF_H + wy + px) * IMG_W + gx] = (uB - mu) * inv_sd;
    }
}

extern "C" void kernel_launch(void* const* d_in, const int* in_sizes, int n_in,
                              void* d_out, int out_size)
{
    const float* image = (const float*)d_in[0];
    const float* mask  = (const float*)d_in[1];
    float* out = (float*)d_out;

    const int img_elems  = in_sizes[0];
    const int mask_elems = in_sizes[1];
    const int planes = img_elems / (IMG_W * IMG_H);

    dim3 block(TS_X, TS_Y);
    dim3 grid(IMG_W / TS_X, IMG_H / TILE_H, planes);
    median7_kernel<<<grid, block>>>(image, out);

    cudaMemcpyAsync(out + img_elems, mask,
                    (size_t)mask_elems * sizeof(float),
                    cudaMemcpyDeviceToDevice, 0);
}

// round 11
// speedup vs baseline: 5.9253x; 1.0082x over previous
#include <cuda_runtime.h>
#include <cuda_fp16.h>
#include <stdint.h>

#define TS_X 32
#define TS_Y 8
#define ROWS_PER_T 4               // output rows per thread (per fp16 lane)
#define HALF_H (TS_Y * ROWS_PER_T) // 32
#define TILE_H (2 * HALF_H)        // 64 output rows per block (2 fp16 lanes)
#define PAD 3
#define SW (TS_X + 2*PAD)          // 38
#define SH (HALF_H + 2*PAD)        // 38
#define IMG_W 512
#define IMG_H 512

__constant__ float c_mean[3] = {0.485f, 0.456f, 0.406f};
__constant__ float c_std[3]  = {0.229f, 0.224f, 0.225f};

// ---------------- compile-time network generation ----------------
struct Op { unsigned char k, a, b; };   // k=0: CE(buf[a],buf[b]); k=1: buf[b]=buf[a]
struct IL { unsigned char v[44]; int n; };
struct Prog { Op ops[900]; int n; unsigned char med[4]; };

__host__ __device__ static constexpr IL make_row(int r) {
    IL x{}; for (int c = 0; c < 7; ++c) x.v[x.n++] = (unsigned char)(r * 7 + c);
    return x;
}

// Batcher odd-even merge of two sorted index lists; emits comparators,
// returns the slot indices in sorted order.
__host__ __device__ static constexpr IL oem(const IL A, const IL B, Prog& P) {
    if (A.n == 0) return B;
    if (B.n == 0) return A;
    IL R{};
    if (A.n == 1 && B.n == 1) {
        P.ops[P.n++] = {0, A.v[0], B.v[0]};
        R.v[0] = A.v[0]; R.v[1] = B.v[0]; R.n = 2; return R;
    }
    IL Ae{}, Ao{}, Be{}, Bo{};
    for (int i = 0; i < A.n; ++i) { if (i % 2 == 0) Ae.v[Ae.n++] = A.v[i]; else Ao.v[Ao.n++] = A.v[i]; }
    for (int i = 0; i < B.n; ++i) { if (i % 2 == 0) Be.v[Be.n++] = B.v[i]; else Bo.v[Bo.n++] = B.v[i]; }
    IL E = oem(Ae, Be, P);
    IL O = oem(Ao, Bo, P);
    R.v[R.n++] = E.v[0];
    int i = 1, j = 0;
    while (i < E.n && j < O.n) {
        P.ops[P.n++] = {0, O.v[j], E.v[i]};     // min -> O slot, max -> E slot
        R.v[R.n++] = O.v[j]; R.v[R.n++] = E.v[i];
        ++i; ++j;
    }
    while (j < O.n) R.v[R.n++] = O.v[j++];
    while (i < E.n) R.v[R.n++] = E.v[i++];
    return R;
}

__host__ __device__ static constexpr IL sort_gen(const IL A, Prog& P) {
    if (A.n <= 1) return A;
    IL L{}, R{};
    const int m = A.n / 2;
    for (int i = 0; i < m;   ++i) L.v[L.n++] = A.v[i];
    for (int i = m; i < A.n; ++i) R.v[R.n++] = A.v[i];
    IL Ls = sort_gen(L, P), Rs = sort_gen(R, P);
    return oem(Ls, Rs, P);
}

__host__ __device__ static constexpr IL copy_gen(const IL A, int dst0, Prog& P) {
    IL R{};
    for (int i = 0; i < A.n; ++i) {
        P.ops[P.n++] = {1, A.v[i], (unsigned char)(dst0 + i)};
        R.v[R.n++] = (unsigned char)(dst0 + i);
    }
    return R;
}

__host__ __device__ static constexpr IL sub(const IL A, int lo, int cnt) {
    IL R{}; for (int i = 0; i < cnt; ++i) R.v[R.n++] = A.v[lo + i]; return R;
}

// Thread does 4 output rows: pairs (0,1) and (2,3). Tile rows 0..9 (relative).
// Pair1 shared rows 1..6, privates rows 0,7. Pair2 shared rows 3..8, privates 2,9.
// Liveness-friendly order: finish pair2 completely before building pair1's
// Ba/F1, so m2/m2c/c2 die early and the peak register window is short.
__host__ __device__ static constexpr Prog build() {
    Prog P{};
    // Center blocks shared by both pairs
    IL L3 = sort_gen(make_row(3), P);
    IL L4 = sort_gen(make_row(4), P);
    IL Bb = oem(L3, L4, P);
    IL L5 = sort_gen(make_row(5), P);
    IL L6 = sort_gen(make_row(6), P);
    IL Bc = oem(L5, L6, P);
    IL M  = oem(Bb, Bc, P);             // sorted 28 (rows 3..6), shared
    IL Mc = copy_gen(M, 84, P);         // preserved copy for pair1
    // ---- pair 2 (windows rows 2..8 and 3..9) ----
    IL L7 = sort_gen(make_row(7), P);
    IL c7 = copy_gen(L7, 77, P);        // row7 is pair1-private too
    IL L8 = sort_gen(make_row(8), P);
    IL Bd = oem(L7, L8, P);
    IL F2 = oem(M, Bd, P);              // sorted 42
    IL m2 = sub(F2, 16, 10);            // ranks 17..26: only possible medians
    IL m2c = copy_gen(m2, 112, P);
    IL L2 = sort_gen(make_row(2), P);
    IL c2 = copy_gen(L2, 70, P);        // row2 also feeds Ba below
    IL G2 = oem(m2, c2, P);  P.med[2] = G2.v[8];   // rank 25 of 49 = rank 9 of 17
    IL L9 = sort_gen(make_row(9), P);
    IL G3 = oem(m2c, L9, P); P.med[3] = G3.v[8];
    // ---- pair 1 (windows rows 0..6 and 1..7) ----
    IL L1 = sort_gen(make_row(1), P);
    IL Ba = oem(L1, L2, P);             // uses original (still sorted) L2 slots
    IL F1 = oem(Mc, Ba, P);             // sorted 42
    IL m1 = sub(F1, 16, 10);
    IL m1c = copy_gen(m1, 122, P);
    IL L0 = sort_gen(make_row(0), P);
    IL G0 = oem(m1, L0, P);  P.med[0] = G0.v[8];
    IL G1 = oem(m1c, c7, P); P.med[1] = G1.v[8];
    return P;
}

// ---------------- kernel ----------------
__device__ __forceinline__ void s2(__half2& a, __half2& b) {
    __half2 mn = __hmin2(a, b);
    b = __hmax2(a, b);
    a = mn;
}

__device__ __forceinline__ int reflect(int v, int n) {
    v = v < 0 ? -v : v;
    return v >= n ? 2 * (n - 1) - v : v;
}

__global__ __launch_bounds__(TS_X * TS_Y, 4) void median7_kernel(
    const float* __restrict__ in, float* __restrict__ out)
{
    // Compile-time evaluated; every access below has a literal index after
    // full unroll, so the network folds to straight-line register code.
    constexpr Prog PROG = build();

    __shared__ __half2 tile[SH][SW];

    const int z = blockIdx.z;
    const int c = z % 3;
    const float* img = in + (size_t)z * (IMG_W * IMG_H);
    float* o = out + (size_t)z * (IMG_W * IMG_H);

    const int tx0 = blockIdx.x * TS_X;
    const int ty0 = blockIdx.y * TILE_H;
    const int tid = threadIdx.y * TS_X + threadIdx.x;

    #pragma unroll
    for (int i = tid; i < SW * SH; i += TS_X * TS_Y) {
        const int r = i / SW, lxx = i % SW;
        const int gx  = reflect(tx0 + lxx - PAD, IMG_W);
        const int gyA = reflect(ty0 + r - PAD, IMG_H);
        const int gyB = reflect(ty0 + HALF_H + r - PAD, IMG_H);
        tile[r][lxx] = __floats2half2_rn(img[gyA * IMG_W + gx], img[gyB * IMG_W + gx]);
    }
    __syncthreads();

    const int lx = threadIdx.x;
    const int wy = ROWS_PER_T * threadIdx.y;   // first output row (tile row offset)

    __half2 buf[132];
    #pragma unroll
    for (int r = 0; r < 10; ++r)
        #pragma unroll
        for (int cc = 0; cc < 7; ++cc)
            buf[r * 7 + cc] = tile[wy + r][lx + cc];

    #pragma unroll
    for (int k = 0; k < PROG.n; ++k) {
        if (PROG.ops[k].k == 0) s2(buf[PROG.ops[k].a], buf[PROG.ops[k].b]);
        else                    buf[PROG.ops[k].b] = buf[PROG.ops[k].a];
    }

    const float mu = c_mean[c], sd = c_std[c];
    const float inv_sd = 1.0f / sd;
    const int gx = tx0 + lx;

    #pragma unroll
    for (int px = 0; px < ROWS_PER_T; ++px) {
        const __half2 med2 = buf[PROG.med[px]];
        const float medA = __low2float(med2);
        const float medB = __high2float(med2);

        float uA = fmaf(medA, sd, mu);
        uA = fminf(fmaxf(uA, 0.0f), 1.0f);
        o[(ty0 + wy + px) * IMG_W + gx] = (uA - mu) * inv_sd;

        float uB = fmaf(medB, sd, mu);
        uB = fminf(fmaxf(uB, 0.0f), 1.0f);
        o[(ty0 + HALF_H + wy + px) * IMG_W + gx] = (uB - mu) * inv_sd;
    }
}

extern "C" void kernel_launch(void* const* d_in, const int* in_sizes, int n_in,
                              void* d_out, int out_size)
{
    const float* image = (const float*)d_in[0];
    const float* mask  = (const float*)d_in[1];
    float* out = (float*)d_out;

    const int img_elems  = in_sizes[0];
    const int mask_elems = in_sizes[1];
    const int planes = img_elems / (IMG_W * IMG_H);

    dim3 block(TS_X, TS_Y);
    dim3 grid(IMG_W / TS_X, IMG_H / TILE_H, planes);
    median7_kernel<<<grid, block>>>(image, out);

    cudaMemcpyAsync(out + img_elems, mask,
                    (size_t)mask_elems * sizeof(float),
                    cudaMemcpyDeviceToDevice, 0);
}